// round 6
// baseline (speedup 1.0000x reference)
#include <cuda_runtime.h>
#include <math.h>
#include <stdint.h>

#define NN    10000
#define EEMAX 320000
#define ETOTM (EEMAX + NN)

// ---------------- scratch (static __device__, 16B aligned, used in-kernel only) ----
__device__ __align__(16) float g_h1[NN * 384];
__device__ __align__(16) float g_s1[NN * 3];
__device__ __align__(16) float g_d1[NN * 3];
__device__ __align__(16) float g_expe1[ETOTM * 3];
__device__ __align__(16) float g_den1[NN * 3];
__device__ __align__(16) float g_agg1[NN * 384];
__device__ __align__(16) float g_h2[NN * 128];
__device__ __align__(16) float g_s2[NN];
__device__ __align__(16) float g_d2[NN];
__device__ __align__(16) float g_expe2[ETOTM];
__device__ __align__(16) float g_den2[NN];
__device__ __align__(16) float g_agg2[NN * 128];
__device__ __align__(16) float g_nattn[NN];
__device__ __align__(16) float g_pool[2 * 256];

// ---------------- zero the per-branch accumulators ----------------
__global__ void zero_scratch(int Ncnt)
{
    int stride = gridDim.x * blockDim.x;
    int i0 = blockIdx.x * blockDim.x + threadIdx.x;
    for (int i = i0; i < Ncnt * 384; i += stride) g_agg1[i] = 0.f;
    for (int i = i0; i < Ncnt * 128; i += stride) g_agg2[i] = 0.f;
    for (int i = i0; i < Ncnt * 3;   i += stride) g_den1[i] = 0.f;
    for (int i = i0; i < Ncnt;       i += stride) { g_den2[i] = 0.f; g_nattn[i] = 0.f; }
}

// ---------------- GEMM1: g_h1[M,384] = x[M,256] @ W1[256,384] ----------------
__global__ __launch_bounds__(256) void gemm_l1(const float* __restrict__ A,
                                               const float* __restrict__ B, int M)
{
    const int N = 384, K = 256;
    __shared__ float As[16][65];
    __shared__ float Bs[16][64];
    const int tid = threadIdx.x;
    const int tx = tid & 15, ty = tid >> 4;
    const int row0 = blockIdx.y * 64, col0 = blockIdx.x * 64;
    float acc[4][4] = {};

    for (int k0 = 0; k0 < K; k0 += 16) {
        #pragma unroll
        for (int i = tid; i < 64 * 16; i += 256) {
            int r = i >> 4, c = i & 15;
            int arow = row0 + r;
            As[c][r] = (arow < M) ? A[(size_t)arow * K + k0 + c] : 0.f;
        }
        #pragma unroll
        for (int i = tid; i < 16 * 64; i += 256) {
            int r = i >> 6, c = i & 63;
            Bs[r][c] = B[(size_t)(k0 + r) * N + col0 + c];
        }
        __syncthreads();

        #pragma unroll
        for (int k = 0; k < 16; k++) {
            float a[4], b[4];
            #pragma unroll
            for (int i = 0; i < 4; i++) a[i] = As[k][ty * 4 + i];
            #pragma unroll
            for (int j = 0; j < 4; j++) b[j] = Bs[k][tx * 4 + j];
            #pragma unroll
            for (int i = 0; i < 4; i++)
                #pragma unroll
                for (int j = 0; j < 4; j++)
                    acc[i][j] += a[i] * b[j];
        }
        __syncthreads();
    }
    #pragma unroll
    for (int i = 0; i < 4; i++) {
        int row = row0 + ty * 4 + i;
        if (row < M) {
            #pragma unroll
            for (int j = 0; j < 4; j++)
                g_h1[(size_t)row * N + col0 + tx * 4 + j] = acc[i][j];
        }
    }
}

// ---------------- GEMM2: g_h2[M,128] = relu(g_agg1 + b1)[M,384] @ W2[384,128] ----
__global__ __launch_bounds__(256) void gemm_l2(const float* __restrict__ B,
                                               const float* __restrict__ abias, int M)
{
    const int N = 128, K = 384;
    __shared__ float As[16][65];
    __shared__ float Bs[16][64];
    const int tid = threadIdx.x;
    const int tx = tid & 15, ty = tid >> 4;
    const int row0 = blockIdx.y * 64, col0 = blockIdx.x * 64;
    float acc[4][4] = {};

    for (int k0 = 0; k0 < K; k0 += 16) {
        #pragma unroll
        for (int i = tid; i < 64 * 16; i += 256) {
            int r = i >> 4, c = i & 15;
            int arow = row0 + r;
            float v = 0.f;
            if (arow < M)
                v = fmaxf(g_agg1[(size_t)arow * K + k0 + c] + abias[k0 + c], 0.f);
            As[c][r] = v;
        }
        #pragma unroll
        for (int i = tid; i < 16 * 64; i += 256) {
            int r = i >> 6, c = i & 63;
            Bs[r][c] = B[(size_t)(k0 + r) * N + col0 + c];
        }
        __syncthreads();

        #pragma unroll
        for (int k = 0; k < 16; k++) {
            float a[4], b[4];
            #pragma unroll
            for (int i = 0; i < 4; i++) a[i] = As[k][ty * 4 + i];
            #pragma unroll
            for (int j = 0; j < 4; j++) b[j] = Bs[k][tx * 4 + j];
            #pragma unroll
            for (int i = 0; i < 4; i++)
                #pragma unroll
                for (int j = 0; j < 4; j++)
                    acc[i][j] += a[i] * b[j];
        }
        __syncthreads();
    }
    #pragma unroll
    for (int i = 0; i < 4; i++) {
        int row = row0 + ty * 4 + i;
        if (row < M) {
            #pragma unroll
            for (int j = 0; j < 4; j++)
                g_h2[(size_t)row * N + col0 + tx * 4 + j] = acc[i][j];
        }
    }
}

// ---------------- s/d layer 1: thread per (node,head), scalar 128-dot ---------
__global__ void sd_l1(const float* __restrict__ asrc, const float* __restrict__ adst, int n)
{
    int t = blockIdx.x * blockDim.x + threadIdx.x;
    if (t >= n * 3) return;
    int hd = t % 3;
    float ss = 0.f, dd = 0.f;
    const float* hv = g_h1 + (size_t)t * 128;
    const float* sa = asrc + hd * 128;
    const float* da = adst + hd * 128;
    #pragma unroll 8
    for (int k = 0; k < 128; k++) {
        float h = hv[k];
        ss += h * sa[k];
        dd += h * da[k];
    }
    g_s1[t] = ss; g_d1[t] = dd;
}

__global__ void sd_l2(const float* __restrict__ asrc, const float* __restrict__ adst, int n)
{
    int t = blockIdx.x * blockDim.x + threadIdx.x;
    if (t >= n) return;
    float ss = 0.f, dd = 0.f;
    const float* hv = g_h2 + (size_t)t * 128;
    #pragma unroll 8
    for (int k = 0; k < 128; k++) {
        float h = hv[k];
        ss += h * asrc[k];
        dd += h * adst[k];
    }
    g_s2[t] = ss; g_d2[t] = dd;
}

// ---------------- edge pass: exp(leaky_relu(s[src]+d[dst])), denom scatter ----
// NOTE: edge_index is int32 (JAX x64 disabled downcasts jnp.int64 -> int32).
__global__ void epass_l1(const int* __restrict__ ei, int E, int Ncnt)
{
    int e = blockIdx.x * blockDim.x + threadIdx.x;
    int Etot = E + Ncnt;
    if (e >= Etot) return;
    int src, dst;
    if (e < E) { src = ei[e]; dst = ei[E + e]; }
    else       { src = e - E; dst = src; }
    src = min(max(src, 0), Ncnt - 1);
    dst = min(max(dst, 0), Ncnt - 1);
    #pragma unroll
    for (int h = 0; h < 3; h++) {
        float v = g_s1[src * 3 + h] + g_d1[dst * 3 + h];
        v = v > 0.f ? v : 0.2f * v;
        float ex = expf(v);
        g_expe1[(size_t)e * 3 + h] = ex;
        atomicAdd(&g_den1[dst * 3 + h], ex);
    }
}

__global__ void epass_l2(const int* __restrict__ ei, int E, int Ncnt)
{
    int e = blockIdx.x * blockDim.x + threadIdx.x;
    int Etot = E + Ncnt;
    if (e >= Etot) return;
    int src, dst;
    if (e < E) { src = ei[e]; dst = ei[E + e]; }
    else       { src = e - E; dst = src; }
    src = min(max(src, 0), Ncnt - 1);
    dst = min(max(dst, 0), Ncnt - 1);
    float v = g_s2[src] + g_d2[dst];
    v = v > 0.f ? v : 0.2f * v;
    float ex = expf(v);
    g_expe2[e] = ex;
    atomicAdd(&g_den2[dst], ex);
}

// ---------------- layer-1 aggregation (warp per edge, heads=3, scalar) --------
__global__ void agg_l1(const int* __restrict__ ei, int E, int Ncnt,
                       float* __restrict__ out, long long alpha_base, long long out_size)
{
    int w = (blockIdx.x * blockDim.x + threadIdx.x) >> 5;
    int lane = threadIdx.x & 31;
    int Etot = E + Ncnt;
    if (w >= Etot) return;
    int src, dst;
    if (w < E) { src = ei[w]; dst = ei[E + w]; }
    else       { src = w - E; dst = src; }
    src = min(max(src, 0), Ncnt - 1);
    dst = min(max(dst, 0), Ncnt - 1);

    float a0 = g_expe1[(size_t)w * 3 + 0] / g_den1[dst * 3 + 0];
    float a1 = g_expe1[(size_t)w * 3 + 1] / g_den1[dst * 3 + 1];
    float a2 = g_expe1[(size_t)w * 3 + 2] / g_den1[dst * 3 + 2];

    if (lane < 3) {
        long long idx = alpha_base + (long long)w * 3 + lane;
        if (idx >= 0 && idx < out_size)
            out[idx] = (lane == 0) ? a0 : ((lane == 1) ? a1 : a2);
    }
    if (lane == 0) atomicAdd(&g_nattn[dst], (a0 + a1 + a2) * (1.0f / 3.0f));

    const float* hs = g_h1 + (size_t)src * 384;
    float* od = g_agg1 + (size_t)dst * 384;
    float al[3] = {a0, a1, a2};
    #pragma unroll
    for (int hd = 0; hd < 3; hd++) {
        float a = al[hd];
        #pragma unroll
        for (int j = 0; j < 4; j++) {
            int idx = hd * 128 + j * 32 + lane;   // coalesced across lanes
            atomicAdd(od + idx, hs[idx] * a);
        }
    }
}

// ---------------- layer-2 aggregation (warp per edge, heads=1, C=128) ---------
__global__ void agg_l2(const int* __restrict__ ei, int E, int Ncnt)
{
    int w = (blockIdx.x * blockDim.x + threadIdx.x) >> 5;
    int lane = threadIdx.x & 31;
    int Etot = E + Ncnt;
    if (w >= Etot) return;
    int src, dst;
    if (w < E) { src = ei[w]; dst = ei[E + w]; }
    else       { src = w - E; dst = src; }
    src = min(max(src, 0), Ncnt - 1);
    dst = min(max(dst, 0), Ncnt - 1);

    float a = g_expe2[w] / g_den2[dst];
    const float* hs = g_h2 + (size_t)src * 128;
    float* od = g_agg2 + (size_t)dst * 128;
    #pragma unroll
    for (int j = 0; j < 4; j++) {
        int idx = j * 32 + lane;
        atomicAdd(od + idx, hs[idx] * a);
    }
}

// ---------------- pooling into g_pool[pool_off .. pool_off+255] ---------------
__global__ void pool_kernel(const float* __restrict__ b2, int Ncnt, int pool_off)
{
    int c = blockIdx.x;  // 0..127
    float bias = b2[c];
    float sw = 0.f, se = 0.f;
    for (int n = threadIdx.x; n < Ncnt; n += blockDim.x) {
        float v = g_agg2[(size_t)n * 128 + c] + bias;
        se += v;
        sw += v * g_nattn[n];
    }
    __shared__ float r0[256], r1[256];
    r0[threadIdx.x] = sw; r1[threadIdx.x] = se;
    __syncthreads();
    for (int o = 128; o; o >>= 1) {
        if (threadIdx.x < o) { r0[threadIdx.x] += r0[threadIdx.x + o]; r1[threadIdx.x] += r1[threadIdx.x + o]; }
        __syncthreads();
    }
    if (threadIdx.x == 0) {
        float inv = 1.0f / (float)Ncnt;
        g_pool[pool_off + c]       = r0[0] * inv;
        g_pool[pool_off + 128 + c] = r1[0] * inv;
    }
}

// ---------------- cosine similarity (guarded write) ----------------
__global__ void sim_kernel(float* __restrict__ out, long long out_size)
{
    int t = threadIdx.x;  // 256 threads
    float a = g_pool[t], b = g_pool[256 + t];
    __shared__ float sd_[256], sa[256], sb[256];
    sd_[t] = a * b; sa[t] = a * a; sb[t] = b * b;
    __syncthreads();
    for (int o = 128; o; o >>= 1) {
        if (t < o) { sd_[t] += sd_[t + o]; sa[t] += sa[t + o]; sb[t] += sb[t + o]; }
        __syncthreads();
    }
    if (t == 0 && out_size >= 1) {
        float n1 = fmaxf(sqrtf(sa[0]), 1e-8f);
        float n2 = fmaxf(sqrtf(sb[0]), 1e-8f);
        out[0] = sd_[0] / (n1 * n2);
    }
}

// ---------------- host launcher: kernel launches ONLY ----------------
extern "C" void kernel_launch(void* const* d_in, const int* in_sizes, int n_in,
                              void* d_out, int out_size)
{
    const float* x1  = (const float*)d_in[0];
    const int*   ei1 = (const int*)d_in[1];     // int32! (JAX x64 disabled)
    const float* x2  = (const float*)d_in[2];
    const int*   ei2 = (const int*)d_in[3];
    const float* W1  = (const float*)d_in[4];
    const float* as1 = (const float*)d_in[5];
    const float* ad1 = (const float*)d_in[6];
    const float* b1  = (const float*)d_in[7];
    const float* W2  = (const float*)d_in[8];
    const float* as2 = (const float*)d_in[9];
    const float* ad2 = (const float*)d_in[10];
    const float* b2  = (const float*)d_in[11];
    float* out = (float*)d_out;
    const long long osz = (long long)out_size;

    const int Ncnt = in_sizes[0] / 256;
    const int E    = in_sizes[1] / 2;
    const int Etot = E + Ncnt;

    const int wblocks = (Etot * 32 + 255) / 256;
    const int eblocks = (Etot + 255) / 256;

    for (int b = 0; b < 2; b++) {
        const float* x  = b ? x2 : x1;
        const int*   ei = b ? ei2 : ei1;
        const long long alpha_base = 1 + (long long)b * Etot * 3;

        zero_scratch<<<1024, 256>>>(Ncnt);

        // layer 1
        gemm_l1<<<dim3(384 / 64, (Ncnt + 63) / 64), 256>>>(x, W1, Ncnt);
        sd_l1<<<(Ncnt * 3 + 255) / 256, 256>>>(as1, ad1, Ncnt);
        epass_l1<<<eblocks, 256>>>(ei, E, Ncnt);
        agg_l1<<<wblocks, 256>>>(ei, E, Ncnt, out, alpha_base, osz);

        // layer 2 (input = relu(agg1 + b1), fused into GEMM A-read)
        gemm_l2<<<dim3(128 / 64, (Ncnt + 63) / 64), 256>>>(W2, b1, Ncnt);
        sd_l2<<<(Ncnt + 255) / 256, 256>>>(as2, ad2, Ncnt);
        epass_l2<<<eblocks, 256>>>(ei, E, Ncnt);
        agg_l2<<<wblocks, 256>>>(ei, E, Ncnt);

        // pooling
        pool_kernel<<<128, 256>>>(b2, Ncnt, b * 256);
    }

    sim_kernel<<<1, 256>>>(out, osz);
}

// round 7
// speedup vs baseline: 1.1673x; 1.1673x over previous
#include <cuda_runtime.h>
#include <math.h>
#include <stdint.h>

#define NN    10000
#define EEMAX 320000
#define ETOTM (EEMAX + NN)

// ---------------- scratch (static __device__, 16B aligned) ----------------
__device__ __align__(16) float g_h1[NN * 384];
__device__ __align__(16) float g_s1[NN * 3];
__device__ __align__(16) float g_d1[NN * 3];
__device__ __align__(16) float g_expe1[ETOTM * 3];
__device__ __align__(16) float g_den1[NN * 3];
__device__ __align__(16) float g_agg1[NN * 384];
__device__ __align__(16) float g_h2[NN * 128];
__device__ __align__(16) float g_s2[NN];
__device__ __align__(16) float g_d2[NN];
__device__ __align__(16) float g_expe2[ETOTM];
__device__ __align__(16) float g_den2[NN];
__device__ __align__(16) float g_agg2[NN * 128];
__device__ __align__(16) float g_nattn[NN];
__device__ __align__(16) float g_pool[2 * 256];

// vectorized fire-and-forget global reduction (sm_90+)
__device__ __forceinline__ void red_add_v4(float* addr, float x, float y, float z, float w)
{
    asm volatile("red.global.add.v4.f32 [%0], {%1, %2, %3, %4};"
                 :: "l"(addr), "f"(x), "f"(y), "f"(z), "f"(w) : "memory");
}

// ---------------- zero the per-branch accumulators (float4) ----------------
__global__ void zero_scratch(int Ncnt)
{
    int stride = gridDim.x * blockDim.x;
    int i0 = blockIdx.x * blockDim.x + threadIdx.x;
    float4 z = make_float4(0.f, 0.f, 0.f, 0.f);
    for (int i = i0; i < Ncnt * 96; i += stride) ((float4*)g_agg1)[i] = z;
    for (int i = i0; i < Ncnt * 32; i += stride) ((float4*)g_agg2)[i] = z;
    for (int i = i0; i < Ncnt * 3;  i += stride) g_den1[i] = 0.f;
    for (int i = i0; i < Ncnt;      i += stride) { g_den2[i] = 0.f; g_nattn[i] = 0.f; }
}

// ---------------- GEMM1: g_h1[M,384] = x[M,256] @ W1[256,384] ----------------
// BM=BN=64, BK=16, 256 threads, 4x4 microtile, float4 loads.
__global__ __launch_bounds__(256) void gemm_l1(const float* __restrict__ A,
                                               const float* __restrict__ B, int M)
{
    const int N = 384, K = 256;
    __shared__ float As[16][65];
    __shared__ float Bs[16][64];
    const int tid = threadIdx.x;
    const int tx = tid & 15, ty = tid >> 4;
    const int row0 = blockIdx.y * 64, col0 = blockIdx.x * 64;
    float acc[4][4] = {};

    for (int k0 = 0; k0 < K; k0 += 16) {
        {   // A tile: 64 rows x 16 k, float4, transposed store
            int ar = tid >> 2, ac = (tid & 3) * 4;
            int arow = row0 + ar;
            float4 av = make_float4(0.f, 0.f, 0.f, 0.f);
            if (arow < M) av = *(const float4*)(A + (size_t)arow * K + k0 + ac);
            As[ac + 0][ar] = av.x; As[ac + 1][ar] = av.y;
            As[ac + 2][ar] = av.z; As[ac + 3][ar] = av.w;
        }
        {   // B tile: 16 k x 64 cols, float4
            int br = tid >> 4, bc = (tid & 15) * 4;
            *(float4*)&Bs[br][bc] = *(const float4*)(B + (size_t)(k0 + br) * N + col0 + bc);
        }
        __syncthreads();

        #pragma unroll
        for (int k = 0; k < 16; k++) {
            float a[4], b[4];
            #pragma unroll
            for (int i = 0; i < 4; i++) a[i] = As[k][ty * 4 + i];
            #pragma unroll
            for (int j = 0; j < 4; j++) b[j] = Bs[k][tx * 4 + j];
            #pragma unroll
            for (int i = 0; i < 4; i++)
                #pragma unroll
                for (int j = 0; j < 4; j++)
                    acc[i][j] += a[i] * b[j];
        }
        __syncthreads();
    }
    #pragma unroll
    for (int i = 0; i < 4; i++) {
        int row = row0 + ty * 4 + i;
        if (row < M)
            *(float4*)(g_h1 + (size_t)row * N + col0 + tx * 4) =
                make_float4(acc[i][0], acc[i][1], acc[i][2], acc[i][3]);
    }
}

// ---------------- GEMM2: g_h2[M,128] = relu(g_agg1 + b1)[M,384] @ W2[384,128] ----
__global__ __launch_bounds__(256) void gemm_l2(const float* __restrict__ B,
                                               const float* __restrict__ abias, int M)
{
    const int N = 128, K = 384;
    __shared__ float As[16][65];
    __shared__ float Bs[16][64];
    const int tid = threadIdx.x;
    const int tx = tid & 15, ty = tid >> 4;
    const int row0 = blockIdx.y * 64, col0 = blockIdx.x * 64;
    float acc[4][4] = {};

    for (int k0 = 0; k0 < K; k0 += 16) {
        {
            int ar = tid >> 2, ac = (tid & 3) * 4;
            int arow = row0 + ar;
            float4 av = make_float4(0.f, 0.f, 0.f, 0.f);
            if (arow < M) {
                av = *(const float4*)(g_agg1 + (size_t)arow * K + k0 + ac);
                av.x = fmaxf(av.x + abias[k0 + ac + 0], 0.f);
                av.y = fmaxf(av.y + abias[k0 + ac + 1], 0.f);
                av.z = fmaxf(av.z + abias[k0 + ac + 2], 0.f);
                av.w = fmaxf(av.w + abias[k0 + ac + 3], 0.f);
            }
            As[ac + 0][ar] = av.x; As[ac + 1][ar] = av.y;
            As[ac + 2][ar] = av.z; As[ac + 3][ar] = av.w;
        }
        {
            int br = tid >> 4, bc = (tid & 15) * 4;
            *(float4*)&Bs[br][bc] = *(const float4*)(B + (size_t)(k0 + br) * N + col0 + bc);
        }
        __syncthreads();

        #pragma unroll
        for (int k = 0; k < 16; k++) {
            float a[4], b[4];
            #pragma unroll
            for (int i = 0; i < 4; i++) a[i] = As[k][ty * 4 + i];
            #pragma unroll
            for (int j = 0; j < 4; j++) b[j] = Bs[k][tx * 4 + j];
            #pragma unroll
            for (int i = 0; i < 4; i++)
                #pragma unroll
                for (int j = 0; j < 4; j++)
                    acc[i][j] += a[i] * b[j];
        }
        __syncthreads();
    }
    #pragma unroll
    for (int i = 0; i < 4; i++) {
        int row = row0 + ty * 4 + i;
        if (row < M)
            *(float4*)(g_h2 + (size_t)row * N + col0 + tx * 4) =
                make_float4(acc[i][0], acc[i][1], acc[i][2], acc[i][3]);
    }
}

// ---------------- s/d: warp per (node,head), float4 + shuffle reduce ---------
__global__ void sd_l1(const float* __restrict__ asrc, const float* __restrict__ adst, int n)
{
    int w = (blockIdx.x * blockDim.x + threadIdx.x) >> 5;
    int lane = threadIdx.x & 31;
    if (w >= n * 3) return;
    int hd = w % 3;
    float4 hv = *(const float4*)(g_h1 + (size_t)w * 128 + lane * 4);
    float4 sa = *(const float4*)(asrc + hd * 128 + lane * 4);
    float4 da = *(const float4*)(adst + hd * 128 + lane * 4);
    float ss = hv.x * sa.x + hv.y * sa.y + hv.z * sa.z + hv.w * sa.w;
    float dd = hv.x * da.x + hv.y * da.y + hv.z * da.z + hv.w * da.w;
    #pragma unroll
    for (int o = 16; o; o >>= 1) {
        ss += __shfl_down_sync(0xffffffffu, ss, o);
        dd += __shfl_down_sync(0xffffffffu, dd, o);
    }
    if (lane == 0) { g_s1[w] = ss; g_d1[w] = dd; }
}

__global__ void sd_l2(const float* __restrict__ asrc, const float* __restrict__ adst, int n)
{
    int w = (blockIdx.x * blockDim.x + threadIdx.x) >> 5;
    int lane = threadIdx.x & 31;
    if (w >= n) return;
    float4 hv = *(const float4*)(g_h2 + (size_t)w * 128 + lane * 4);
    float4 sa = *(const float4*)(asrc + lane * 4);
    float4 da = *(const float4*)(adst + lane * 4);
    float ss = hv.x * sa.x + hv.y * sa.y + hv.z * sa.z + hv.w * sa.w;
    float dd = hv.x * da.x + hv.y * da.y + hv.z * da.z + hv.w * da.w;
    #pragma unroll
    for (int o = 16; o; o >>= 1) {
        ss += __shfl_down_sync(0xffffffffu, ss, o);
        dd += __shfl_down_sync(0xffffffffu, dd, o);
    }
    if (lane == 0) { g_s2[w] = ss; g_d2[w] = dd; }
}

// ---------------- edge pass: exp(leaky_relu(s[src]+d[dst])), denom scatter ----
// edge_index is int32 (JAX x64 disabled).
__global__ void epass_l1(const int* __restrict__ ei, int E, int Ncnt)
{
    int e = blockIdx.x * blockDim.x + threadIdx.x;
    int Etot = E + Ncnt;
    if (e >= Etot) return;
    int src, dst;
    if (e < E) { src = ei[e]; dst = ei[E + e]; }
    else       { src = e - E; dst = src; }
    src = min(max(src, 0), Ncnt - 1);
    dst = min(max(dst, 0), Ncnt - 1);
    #pragma unroll
    for (int h = 0; h < 3; h++) {
        float v = g_s1[src * 3 + h] + g_d1[dst * 3 + h];
        v = v > 0.f ? v : 0.2f * v;
        float ex = expf(v);
        g_expe1[(size_t)e * 3 + h] = ex;
        atomicAdd(&g_den1[dst * 3 + h], ex);
    }
}

__global__ void epass_l2(const int* __restrict__ ei, int E, int Ncnt)
{
    int e = blockIdx.x * blockDim.x + threadIdx.x;
    int Etot = E + Ncnt;
    if (e >= Etot) return;
    int src, dst;
    if (e < E) { src = ei[e]; dst = ei[E + e]; }
    else       { src = e - E; dst = src; }
    src = min(max(src, 0), Ncnt - 1);
    dst = min(max(dst, 0), Ncnt - 1);
    float v = g_s2[src] + g_d2[dst];
    v = v > 0.f ? v : 0.2f * v;
    float ex = expf(v);
    g_expe2[e] = ex;
    atomicAdd(&g_den2[dst], ex);
}

// ---------------- layer-1 aggregation (warp per edge, heads=3, red.v4) --------
__global__ void agg_l1(const int* __restrict__ ei, int E, int Ncnt,
                       float* __restrict__ out, long long alpha_base, long long out_size)
{
    int w = (blockIdx.x * blockDim.x + threadIdx.x) >> 5;
    int lane = threadIdx.x & 31;
    int Etot = E + Ncnt;
    if (w >= Etot) return;
    int src, dst;
    if (w < E) { src = ei[w]; dst = ei[E + w]; }
    else       { src = w - E; dst = src; }
    src = min(max(src, 0), Ncnt - 1);
    dst = min(max(dst, 0), Ncnt - 1);

    float a0 = g_expe1[(size_t)w * 3 + 0] / g_den1[dst * 3 + 0];
    float a1 = g_expe1[(size_t)w * 3 + 1] / g_den1[dst * 3 + 1];
    float a2 = g_expe1[(size_t)w * 3 + 2] / g_den1[dst * 3 + 2];

    if (lane < 3) {
        long long idx = alpha_base + (long long)w * 3 + lane;
        if (idx >= 0 && idx < out_size)
            out[idx] = (lane == 0) ? a0 : ((lane == 1) ? a1 : a2);
    }
    if (lane == 0) atomicAdd(&g_nattn[dst], (a0 + a1 + a2) * (1.0f / 3.0f));

    const float4* hs = (const float4*)(g_h1 + (size_t)src * 384);
    float* od = g_agg1 + (size_t)dst * 384;
    float al[3] = {a0, a1, a2};
    #pragma unroll
    for (int hd = 0; hd < 3; hd++) {
        float4 v = hs[hd * 32 + lane];
        float a = al[hd];
        red_add_v4(od + hd * 128 + lane * 4, v.x * a, v.y * a, v.z * a, v.w * a);
    }
}

// ---------------- layer-2 aggregation (warp per edge, C=128, red.v4) ---------
__global__ void agg_l2(const int* __restrict__ ei, int E, int Ncnt)
{
    int w = (blockIdx.x * blockDim.x + threadIdx.x) >> 5;
    int lane = threadIdx.x & 31;
    int Etot = E + Ncnt;
    if (w >= Etot) return;
    int src, dst;
    if (w < E) { src = ei[w]; dst = ei[E + w]; }
    else       { src = w - E; dst = src; }
    src = min(max(src, 0), Ncnt - 1);
    dst = min(max(dst, 0), Ncnt - 1);

    float a = g_expe2[w] / g_den2[dst];
    float4 v = ((const float4*)(g_h2 + (size_t)src * 128))[lane];
    red_add_v4(g_agg2 + (size_t)dst * 128 + lane * 4, v.x * a, v.y * a, v.z * a, v.w * a);
}

// ---------------- pooling into g_pool[pool_off .. pool_off+255] ---------------
__global__ void pool_kernel(const float* __restrict__ b2, int Ncnt, int pool_off)
{
    int c = blockIdx.x;  // 0..127
    float bias = b2[c];
    float sw = 0.f, se = 0.f;
    for (int n = threadIdx.x; n < Ncnt; n += blockDim.x) {
        float v = g_agg2[(size_t)n * 128 + c] + bias;
        se += v;
        sw += v * g_nattn[n];
    }
    __shared__ float r0[256], r1[256];
    r0[threadIdx.x] = sw; r1[threadIdx.x] = se;
    __syncthreads();
    for (int o = 128; o; o >>= 1) {
        if (threadIdx.x < o) { r0[threadIdx.x] += r0[threadIdx.x + o]; r1[threadIdx.x] += r1[threadIdx.x + o]; }
        __syncthreads();
    }
    if (threadIdx.x == 0) {
        float inv = 1.0f / (float)Ncnt;
        g_pool[pool_off + c]       = r0[0] * inv;
        g_pool[pool_off + 128 + c] = r1[0] * inv;
    }
}

// ---------------- cosine similarity (guarded write) ----------------
__global__ void sim_kernel(float* __restrict__ out, long long out_size)
{
    int t = threadIdx.x;  // 256 threads
    float a = g_pool[t], b = g_pool[256 + t];
    __shared__ float sd_[256], sa[256], sb[256];
    sd_[t] = a * b; sa[t] = a * a; sb[t] = b * b;
    __syncthreads();
    for (int o = 128; o; o >>= 1) {
        if (t < o) { sd_[t] += sd_[t + o]; sa[t] += sa[t + o]; sb[t] += sb[t + o]; }
        __syncthreads();
    }
    if (t == 0 && out_size >= 1) {
        float n1 = fmaxf(sqrtf(sa[0]), 1e-8f);
        float n2 = fmaxf(sqrtf(sb[0]), 1e-8f);
        out[0] = sd_[0] / (n1 * n2);
    }
}

// ---------------- host launcher: kernel launches ONLY ----------------
extern "C" void kernel_launch(void* const* d_in, const int* in_sizes, int n_in,
                              void* d_out, int out_size)
{
    const float* x1  = (const float*)d_in[0];
    const int*   ei1 = (const int*)d_in[1];     // int32
    const float* x2  = (const float*)d_in[2];
    const int*   ei2 = (const int*)d_in[3];
    const float* W1  = (const float*)d_in[4];
    const float* as1 = (const float*)d_in[5];
    const float* ad1 = (const float*)d_in[6];
    const float* b1  = (const float*)d_in[7];
    const float* W2  = (const float*)d_in[8];
    const float* as2 = (const float*)d_in[9];
    const float* ad2 = (const float*)d_in[10];
    const float* b2  = (const float*)d_in[11];
    float* out = (float*)d_out;
    const long long osz = (long long)out_size;

    const int Ncnt = in_sizes[0] / 256;
    const int E    = in_sizes[1] / 2;
    const int Etot = E + Ncnt;

    const int wblocks = (Etot * 32 + 255) / 256;
    const int eblocks = (Etot + 255) / 256;

    for (int b = 0; b < 2; b++) {
        const float* x  = b ? x2 : x1;
        const int*   ei = b ? ei2 : ei1;
        const long long alpha_base = 1 + (long long)b * Etot * 3;

        zero_scratch<<<1024, 256>>>(Ncnt);

        // layer 1
        gemm_l1<<<dim3(384 / 64, (Ncnt + 63) / 64), 256>>>(x, W1, Ncnt);
        sd_l1<<<(Ncnt * 3 * 32 + 255) / 256, 256>>>(as1, ad1, Ncnt);
        epass_l1<<<eblocks, 256>>>(ei, E, Ncnt);
        agg_l1<<<wblocks, 256>>>(ei, E, Ncnt, out, alpha_base, osz);

        // layer 2 (input = relu(agg1 + b1), fused into GEMM A-read)
        gemm_l2<<<dim3(128 / 64, (Ncnt + 63) / 64), 256>>>(W2, b1, Ncnt);
        sd_l2<<<(Ncnt * 32 + 255) / 256, 256>>>(as2, ad2, Ncnt);
        epass_l2<<<eblocks, 256>>>(ei, E, Ncnt);
        agg_l2<<<wblocks, 256>>>(ei, E, Ncnt);

        // pooling
        pool_kernel<<<128, 256>>>(b2, Ncnt, b * 256);
    }

    sim_kernel<<<1, 256>>>(out, osz);
}

// round 8
// speedup vs baseline: 1.2691x; 1.0872x over previous
#include <cuda_runtime.h>
#include <math.h>
#include <stdint.h>

#define NN    10000
#define EEMAX 320000
#define ETOTM (EEMAX + NN)

// ---------------- scratch (static __device__, 16B aligned) ----------------
__device__ __align__(16) float g_h1[NN * 384];
__device__ __align__(16) float g_s1[NN * 3];
__device__ __align__(16) float g_d1[NN * 3];
__device__ __align__(16) float g_agg1[NN * 384];
__device__ __align__(16) float g_h2[NN * 128];
__device__ __align__(16) float g_s2[NN];
__device__ __align__(16) float g_d2[NN];
__device__ __align__(16) float g_expe2[ETOTM];
__device__ __align__(16) float g_agg2[NN * 128];
__device__ __align__(16) float g_nattn[NN];
__device__ __align__(16) float g_pool[2 * 256];
// CSR (per branch, rebuilt)
__device__ int g_deg[NN];
__device__ int g_off[NN + 1];
__device__ int g_fill[NN];
__device__ int g_eid[ETOTM];

// ---------------- CSR build ----------------
__global__ void zero_deg(int Ncnt)
{
    int i = blockIdx.x * blockDim.x + threadIdx.x;
    if (i < Ncnt) g_deg[i] = 0;
}

__global__ void csr_count(const int* __restrict__ ei, int E, int Ncnt)
{
    int e = blockIdx.x * blockDim.x + threadIdx.x;
    int Etot = E + Ncnt;
    if (e >= Etot) return;
    int dst = (e < E) ? ei[E + e] : (e - E);
    dst = min(max(dst, 0), Ncnt - 1);
    atomicAdd(&g_deg[dst], 1);
}

// single block, 1024 threads: exclusive scan of g_deg -> g_off / g_fill
__global__ void csr_scan(int Ncnt, int Etot)
{
    __shared__ int part[1024];
    int t = threadIdx.x;
    int chunk = (Ncnt + 1023) / 1024;
    int b = t * chunk;
    int e = min(b + chunk, Ncnt);
    int s = 0;
    for (int i = b; i < e; i++) s += g_deg[i];
    part[t] = s;
    __syncthreads();
    // Hillis-Steele inclusive scan
    for (int o = 1; o < 1024; o <<= 1) {
        int v = (t >= o) ? part[t - o] : 0;
        __syncthreads();
        part[t] += v;
        __syncthreads();
    }
    int off = part[t] - s;   // exclusive prefix
    for (int i = b; i < e; i++) {
        g_off[i] = off;
        g_fill[i] = off;
        off += g_deg[i];
    }
    if (t == 0) g_off[Ncnt] = Etot;
}

__global__ void csr_scatter(const int* __restrict__ ei, int E, int Ncnt)
{
    int e = blockIdx.x * blockDim.x + threadIdx.x;
    int Etot = E + Ncnt;
    if (e >= Etot) return;
    int dst = (e < E) ? ei[E + e] : (e - E);
    dst = min(max(dst, 0), Ncnt - 1);
    int pos = atomicAdd(&g_fill[dst], 1);
    g_eid[pos] = e;
}

// ---------------- GEMM1: g_h1[M,384] = x[M,256] @ W1[256,384] ----------------
__global__ __launch_bounds__(256) void gemm_l1(const float* __restrict__ A,
                                               const float* __restrict__ B, int M)
{
    const int N = 384, K = 256;
    __shared__ float As[16][65];
    __shared__ float Bs[16][64];
    const int tid = threadIdx.x;
    const int tx = tid & 15, ty = tid >> 4;
    const int row0 = blockIdx.y * 64, col0 = blockIdx.x * 64;
    float acc[4][4] = {};

    for (int k0 = 0; k0 < K; k0 += 16) {
        {
            int ar = tid >> 2, ac = (tid & 3) * 4;
            int arow = row0 + ar;
            float4 av = make_float4(0.f, 0.f, 0.f, 0.f);
            if (arow < M) av = *(const float4*)(A + (size_t)arow * K + k0 + ac);
            As[ac + 0][ar] = av.x; As[ac + 1][ar] = av.y;
            As[ac + 2][ar] = av.z; As[ac + 3][ar] = av.w;
        }
        {
            int br = tid >> 4, bc = (tid & 15) * 4;
            *(float4*)&Bs[br][bc] = *(const float4*)(B + (size_t)(k0 + br) * N + col0 + bc);
        }
        __syncthreads();

        #pragma unroll
        for (int k = 0; k < 16; k++) {
            float a[4], b[4];
            #pragma unroll
            for (int i = 0; i < 4; i++) a[i] = As[k][ty * 4 + i];
            #pragma unroll
            for (int j = 0; j < 4; j++) b[j] = Bs[k][tx * 4 + j];
            #pragma unroll
            for (int i = 0; i < 4; i++)
                #pragma unroll
                for (int j = 0; j < 4; j++)
                    acc[i][j] += a[i] * b[j];
        }
        __syncthreads();
    }
    #pragma unroll
    for (int i = 0; i < 4; i++) {
        int row = row0 + ty * 4 + i;
        if (row < M)
            *(float4*)(g_h1 + (size_t)row * N + col0 + tx * 4) =
                make_float4(acc[i][0], acc[i][1], acc[i][2], acc[i][3]);
    }
}

// ---------------- GEMM2: g_h2[M,128] = relu(g_agg1 + b1)[M,384] @ W2[384,128] ----
__global__ __launch_bounds__(256) void gemm_l2(const float* __restrict__ B,
                                               const float* __restrict__ abias, int M)
{
    const int N = 128, K = 384;
    __shared__ float As[16][65];
    __shared__ float Bs[16][64];
    const int tid = threadIdx.x;
    const int tx = tid & 15, ty = tid >> 4;
    const int row0 = blockIdx.y * 64, col0 = blockIdx.x * 64;
    float acc[4][4] = {};

    for (int k0 = 0; k0 < K; k0 += 16) {
        {
            int ar = tid >> 2, ac = (tid & 3) * 4;
            int arow = row0 + ar;
            float4 av = make_float4(0.f, 0.f, 0.f, 0.f);
            if (arow < M) {
                av = *(const float4*)(g_agg1 + (size_t)arow * K + k0 + ac);
                av.x = fmaxf(av.x + abias[k0 + ac + 0], 0.f);
                av.y = fmaxf(av.y + abias[k0 + ac + 1], 0.f);
                av.z = fmaxf(av.z + abias[k0 + ac + 2], 0.f);
                av.w = fmaxf(av.w + abias[k0 + ac + 3], 0.f);
            }
            As[ac + 0][ar] = av.x; As[ac + 1][ar] = av.y;
            As[ac + 2][ar] = av.z; As[ac + 3][ar] = av.w;
        }
        {
            int br = tid >> 4, bc = (tid & 15) * 4;
            *(float4*)&Bs[br][bc] = *(const float4*)(B + (size_t)(k0 + br) * N + col0 + bc);
        }
        __syncthreads();

        #pragma unroll
        for (int k = 0; k < 16; k++) {
            float a[4], b[4];
            #pragma unroll
            for (int i = 0; i < 4; i++) a[i] = As[k][ty * 4 + i];
            #pragma unroll
            for (int j = 0; j < 4; j++) b[j] = Bs[k][tx * 4 + j];
            #pragma unroll
            for (int i = 0; i < 4; i++)
                #pragma unroll
                for (int j = 0; j < 4; j++)
                    acc[i][j] += a[i] * b[j];
        }
        __syncthreads();
    }
    #pragma unroll
    for (int i = 0; i < 4; i++) {
        int row = row0 + ty * 4 + i;
        if (row < M)
            *(float4*)(g_h2 + (size_t)row * N + col0 + tx * 4) =
                make_float4(acc[i][0], acc[i][1], acc[i][2], acc[i][3]);
    }
}

// ---------------- s/d: warp per (node,head), float4 + shuffle reduce ---------
__global__ void sd_l1(const float* __restrict__ asrc, const float* __restrict__ adst, int n)
{
    int w = (blockIdx.x * blockDim.x + threadIdx.x) >> 5;
    int lane = threadIdx.x & 31;
    if (w >= n * 3) return;
    int hd = w % 3;
    float4 hv = *(const float4*)(g_h1 + (size_t)w * 128 + lane * 4);
    float4 sa = *(const float4*)(asrc + hd * 128 + lane * 4);
    float4 da = *(const float4*)(adst + hd * 128 + lane * 4);
    float ss = hv.x * sa.x + hv.y * sa.y + hv.z * sa.z + hv.w * sa.w;
    float dd = hv.x * da.x + hv.y * da.y + hv.z * da.z + hv.w * da.w;
    #pragma unroll
    for (int o = 16; o; o >>= 1) {
        ss += __shfl_down_sync(0xffffffffu, ss, o);
        dd += __shfl_down_sync(0xffffffffu, dd, o);
    }
    if (lane == 0) { g_s1[w] = ss; g_d1[w] = dd; }
}

__global__ void sd_l2(const float* __restrict__ asrc, const float* __restrict__ adst, int n)
{
    int w = (blockIdx.x * blockDim.x + threadIdx.x) >> 5;
    int lane = threadIdx.x & 31;
    if (w >= n) return;
    float4 hv = *(const float4*)(g_h2 + (size_t)w * 128 + lane * 4);
    float4 sa = *(const float4*)(asrc + lane * 4);
    float4 da = *(const float4*)(adst + lane * 4);
    float ss = hv.x * sa.x + hv.y * sa.y + hv.z * sa.z + hv.w * sa.w;
    float dd = hv.x * da.x + hv.y * da.y + hv.z * da.z + hv.w * da.w;
    #pragma unroll
    for (int o = 16; o; o >>= 1) {
        ss += __shfl_down_sync(0xffffffffu, ss, o);
        dd += __shfl_down_sync(0xffffffffu, dd, o);
    }
    if (lane == 0) { g_s2[w] = ss; g_d2[w] = dd; }
}

// ---------------- layer-1 softmax + aggregation: warp per dst node -----------
// Pass A: compute exp per edge -> store to out (alpha slots), reduce den.
// Pass B: alpha = ex/den, write alpha, gather h1[src] and accumulate (no atomics).
__global__ __launch_bounds__(256) void agg_l1_csr(const int* __restrict__ ei, int E, int Ncnt,
                                                  float* __restrict__ out,
                                                  long long alpha_base, long long out_size)
{
    int dst = (blockIdx.x * blockDim.x + threadIdx.x) >> 5;
    int lane = threadIdx.x & 31;
    if (dst >= Ncnt) return;
    int beg = g_off[dst], end = g_off[dst + 1];

    float dv0 = g_d1[dst * 3 + 0], dv1 = g_d1[dst * 3 + 1], dv2 = g_d1[dst * 3 + 2];

    // pass A: exp + den
    float den0 = 0.f, den1 = 0.f, den2 = 0.f;
    for (int i = beg + lane; i < end; i += 32) {
        int eid = g_eid[i];
        int src = (eid < E) ? ei[eid] : (eid - E);
        src = min(max(src, 0), Ncnt - 1);
        float e0 = g_s1[src * 3 + 0] + dv0;
        float e1 = g_s1[src * 3 + 1] + dv1;
        float e2 = g_s1[src * 3 + 2] + dv2;
        e0 = e0 > 0.f ? e0 : 0.2f * e0;
        e1 = e1 > 0.f ? e1 : 0.2f * e1;
        e2 = e2 > 0.f ? e2 : 0.2f * e2;
        float x0 = expf(e0), x1 = expf(e1), x2 = expf(e2);
        long long ob = alpha_base + 3LL * eid;
        if (ob + 2 < out_size) { out[ob] = x0; out[ob + 1] = x1; out[ob + 2] = x2; }
        den0 += x0; den1 += x1; den2 += x2;
    }
    #pragma unroll
    for (int o = 16; o; o >>= 1) {
        den0 += __shfl_xor_sync(0xffffffffu, den0, o);
        den1 += __shfl_xor_sync(0xffffffffu, den1, o);
        den2 += __shfl_xor_sync(0xffffffffu, den2, o);
    }
    float r0 = 1.f / den0, r1 = 1.f / den1, r2 = 1.f / den2;
    __syncwarp();

    // pass B: normalize alpha (write), gather + accumulate
    float acc[12];
    #pragma unroll
    for (int k = 0; k < 12; k++) acc[k] = 0.f;
    float nat = 0.f;

    for (int i = beg; i < end; i++) {
        int eid = g_eid[i];
        int src = (eid < E) ? ei[eid] : (eid - E);
        src = min(max(src, 0), Ncnt - 1);
        long long ob = alpha_base + 3LL * eid;
        float a0 = 0.f, a1 = 0.f, a2 = 0.f;
        if (ob + 2 < out_size) {
            a0 = out[ob] * r0; a1 = out[ob + 1] * r1; a2 = out[ob + 2] * r2;
            if (lane == 0) { out[ob] = a0; out[ob + 1] = a1; out[ob + 2] = a2; }
        }
        nat += (a0 + a1 + a2) * (1.0f / 3.0f);

        const float4* hs = (const float4*)(g_h1 + (size_t)src * 384);
        float4 v0 = hs[lane];
        float4 v1 = hs[32 + lane];
        float4 v2 = hs[64 + lane];
        acc[0] += v0.x * a0; acc[1]  += v0.y * a0; acc[2]  += v0.z * a0; acc[3]  += v0.w * a0;
        acc[4] += v1.x * a1; acc[5]  += v1.y * a1; acc[6]  += v1.z * a1; acc[7]  += v1.w * a1;
        acc[8] += v2.x * a2; acc[9]  += v2.y * a2; acc[10] += v2.z * a2; acc[11] += v2.w * a2;
    }

    if (lane == 0) g_nattn[dst] = nat;
    float4* og = (float4*)(g_agg1 + (size_t)dst * 384);
    og[lane]      = make_float4(acc[0], acc[1], acc[2], acc[3]);
    og[32 + lane] = make_float4(acc[4], acc[5], acc[6], acc[7]);
    og[64 + lane] = make_float4(acc[8], acc[9], acc[10], acc[11]);
}

// ---------------- layer-2 softmax + aggregation: warp per dst node -----------
__global__ __launch_bounds__(256) void agg_l2_csr(const int* __restrict__ ei, int E, int Ncnt)
{
    int dst = (blockIdx.x * blockDim.x + threadIdx.x) >> 5;
    int lane = threadIdx.x & 31;
    if (dst >= Ncnt) return;
    int beg = g_off[dst], end = g_off[dst + 1];

    float dv = g_d2[dst];
    float den = 0.f;
    for (int i = beg + lane; i < end; i += 32) {
        int eid = g_eid[i];
        int src = (eid < E) ? ei[eid] : (eid - E);
        src = min(max(src, 0), Ncnt - 1);
        float e = g_s2[src] + dv;
        e = e > 0.f ? e : 0.2f * e;
        float x = expf(e);
        g_expe2[eid] = x;
        den += x;
    }
    #pragma unroll
    for (int o = 16; o; o >>= 1) den += __shfl_xor_sync(0xffffffffu, den, o);
    float r = 1.f / den;
    __syncwarp();

    float4 acc = make_float4(0.f, 0.f, 0.f, 0.f);
    for (int i = beg; i < end; i++) {
        int eid = g_eid[i];
        int src = (eid < E) ? ei[eid] : (eid - E);
        src = min(max(src, 0), Ncnt - 1);
        float a = g_expe2[eid] * r;
        float4 v = ((const float4*)(g_h2 + (size_t)src * 128))[lane];
        acc.x += v.x * a; acc.y += v.y * a; acc.z += v.z * a; acc.w += v.w * a;
    }
    ((float4*)(g_agg2 + (size_t)dst * 128))[lane] = acc;
}

// ---------------- pooling into g_pool[pool_off .. pool_off+255] ---------------
__global__ void pool_kernel(const float* __restrict__ b2, int Ncnt, int pool_off)
{
    int c = blockIdx.x;  // 0..127
    float bias = b2[c];
    float sw = 0.f, se = 0.f;
    for (int n = threadIdx.x; n < Ncnt; n += blockDim.x) {
        float v = g_agg2[(size_t)n * 128 + c] + bias;
        se += v;
        sw += v * g_nattn[n];
    }
    __shared__ float r0[256], r1[256];
    r0[threadIdx.x] = sw; r1[threadIdx.x] = se;
    __syncthreads();
    for (int o = 128; o; o >>= 1) {
        if (threadIdx.x < o) { r0[threadIdx.x] += r0[threadIdx.x + o]; r1[threadIdx.x] += r1[threadIdx.x + o]; }
        __syncthreads();
    }
    if (threadIdx.x == 0) {
        float inv = 1.0f / (float)Ncnt;
        g_pool[pool_off + c]       = r0[0] * inv;
        g_pool[pool_off + 128 + c] = r1[0] * inv;
    }
}

// ---------------- cosine similarity (guarded write) ----------------
__global__ void sim_kernel(float* __restrict__ out, long long out_size)
{
    int t = threadIdx.x;  // 256 threads
    float a = g_pool[t], b = g_pool[256 + t];
    __shared__ float sd_[256], sa[256], sb[256];
    sd_[t] = a * b; sa[t] = a * a; sb[t] = b * b;
    __syncthreads();
    for (int o = 128; o; o >>= 1) {
        if (t < o) { sd_[t] += sd_[t + o]; sa[t] += sa[t + o]; sb[t] += sb[t + o]; }
        __syncthreads();
    }
    if (t == 0 && out_size >= 1) {
        float n1 = fmaxf(sqrtf(sa[0]), 1e-8f);
        float n2 = fmaxf(sqrtf(sb[0]), 1e-8f);
        out[0] = sd_[0] / (n1 * n2);
    }
}

// ---------------- host launcher: kernel launches ONLY ----------------
extern "C" void kernel_launch(void* const* d_in, const int* in_sizes, int n_in,
                              void* d_out, int out_size)
{
    const float* x1  = (const float*)d_in[0];
    const int*   ei1 = (const int*)d_in[1];     // int32
    const float* x2  = (const float*)d_in[2];
    const int*   ei2 = (const int*)d_in[3];
    const float* W1  = (const float*)d_in[4];
    const float* as1 = (const float*)d_in[5];
    const float* ad1 = (const float*)d_in[6];
    const float* b1  = (const float*)d_in[7];
    const float* W2  = (const float*)d_in[8];
    const float* as2 = (const float*)d_in[9];
    const float* ad2 = (const float*)d_in[10];
    const float* b2  = (const float*)d_in[11];
    float* out = (float*)d_out;
    const long long osz = (long long)out_size;

    const int Ncnt = in_sizes[0] / 256;
    const int E    = in_sizes[1] / 2;
    const int Etot = E + Ncnt;

    const int eblocks = (Etot + 255) / 256;
    const int nwarp_blocks = (Ncnt * 32 + 255) / 256;

    for (int b = 0; b < 2; b++) {
        const float* x  = b ? x2 : x1;
        const int*   ei = b ? ei2 : ei1;
        const long long alpha_base = 1 + (long long)b * Etot * 3;

        // CSR build (shared by both layers)
        zero_deg<<<(Ncnt + 255) / 256, 256>>>(Ncnt);
        csr_count<<<eblocks, 256>>>(ei, E, Ncnt);
        csr_scan<<<1, 1024>>>(Ncnt, Etot);
        csr_scatter<<<eblocks, 256>>>(ei, E, Ncnt);

        // layer 1
        gemm_l1<<<dim3(384 / 64, (Ncnt + 63) / 64), 256>>>(x, W1, Ncnt);
        sd_l1<<<(Ncnt * 3 * 32 + 255) / 256, 256>>>(as1, ad1, Ncnt);
        agg_l1_csr<<<nwarp_blocks, 256>>>(ei, E, Ncnt, out, alpha_base, osz);

        // layer 2 (input = relu(agg1 + b1), fused into GEMM A-read)
        gemm_l2<<<dim3(128 / 64, (Ncnt + 63) / 64), 256>>>(W2, b1, Ncnt);
        sd_l2<<<(Ncnt * 32 + 255) / 256, 256>>>(as2, ad2, Ncnt);
        agg_l2_csr<<<nwarp_blocks, 256>>>(ei, E, Ncnt);

        // pooling
        pool_kernel<<<128, 256>>>(b2, Ncnt, b * 256);
    }

    sim_kernel<<<1, 256>>>(out, osz);
}

// round 9
// speedup vs baseline: 1.3580x; 1.0700x over previous
#include <cuda_runtime.h>
#include <math.h>
#include <stdint.h>

#define NN    10000
#define EEMAX 320000
#define ETOTM (EEMAX + NN)

// ---------------- scratch (static __device__, 16B aligned) ----------------
__device__ __align__(16) float g_h1[NN * 384];
__device__ __align__(16) float g_s1[NN * 3];
__device__ __align__(16) float g_d1[NN * 3];
__device__ __align__(16) float g_agg1[NN * 384];
__device__ __align__(16) float g_h2[NN * 128];
__device__ __align__(16) float g_s2[NN];
__device__ __align__(16) float g_d2[NN];
__device__ __align__(16) float g_expe2[ETOTM];
__device__ __align__(16) float g_agg2[NN * 128];
__device__ __align__(16) float g_nattn[NN];
__device__ __align__(16) float g_pool[2 * 256];
// CSR (per branch, rebuilt)
__device__ int g_deg[NN];
__device__ int g_off[NN + 1];
__device__ int g_fill[NN];
__device__ int g_eid[ETOTM];
__device__ int g_esrc[ETOTM];   // src node per CSR slot (kills indirect loads)

// ---------------- CSR build ----------------
__global__ void zero_deg(int Ncnt)
{
    int i = blockIdx.x * blockDim.x + threadIdx.x;
    if (i < Ncnt) g_deg[i] = 0;
}

__global__ void csr_count(const int* __restrict__ ei, int E, int Ncnt)
{
    int e = blockIdx.x * blockDim.x + threadIdx.x;
    int Etot = E + Ncnt;
    if (e >= Etot) return;
    int dst = (e < E) ? ei[E + e] : (e - E);
    dst = min(max(dst, 0), Ncnt - 1);
    atomicAdd(&g_deg[dst], 1);
}

// single block, 1024 threads: exclusive scan of g_deg -> g_off / g_fill
__global__ void csr_scan(int Ncnt, int Etot)
{
    __shared__ int part[1024];
    int t = threadIdx.x;
    int chunk = (Ncnt + 1023) / 1024;
    int b = t * chunk;
    int e = min(b + chunk, Ncnt);
    int s = 0;
    for (int i = b; i < e; i++) s += g_deg[i];
    part[t] = s;
    __syncthreads();
    for (int o = 1; o < 1024; o <<= 1) {
        int v = (t >= o) ? part[t - o] : 0;
        __syncthreads();
        part[t] += v;
        __syncthreads();
    }
    int off = part[t] - s;   // exclusive prefix
    for (int i = b; i < e; i++) {
        g_off[i] = off;
        g_fill[i] = off;
        off += g_deg[i];
    }
    if (t == 0) g_off[Ncnt] = Etot;
}

__global__ void csr_scatter(const int* __restrict__ ei, int E, int Ncnt)
{
    int e = blockIdx.x * blockDim.x + threadIdx.x;
    int Etot = E + Ncnt;
    if (e >= Etot) return;
    int src, dst;
    if (e < E) { src = ei[e]; dst = ei[E + e]; }
    else       { src = e - E; dst = src; }
    src = min(max(src, 0), Ncnt - 1);
    dst = min(max(dst, 0), Ncnt - 1);
    int pos = atomicAdd(&g_fill[dst], 1);
    g_eid[pos] = e;
    g_esrc[pos] = src;
}

// ---------------- GEMM1: g_h1[M,384] = x[M,256] @ W1[256,384] ----------------
// BM=128, BN=128, BK=8, 256 threads, 8x8 microtile.
__global__ __launch_bounds__(256) void gemm_l1(const float* __restrict__ A,
                                               const float* __restrict__ B, int M)
{
    const int N = 384, K = 256;
    __shared__ float As[8][132];
    __shared__ float Bs[8][128];
    const int tid = threadIdx.x;
    const int tx = tid & 15, ty = tid >> 4;       // 16x16 thread grid
    const int row0 = blockIdx.y * 128, col0 = blockIdx.x * 128;
    float acc[8][8] = {};

    for (int k0 = 0; k0 < K; k0 += 8) {
        {   // A tile: 128 rows x 8 k; thread -> row tid/2, cols (tid&1)*4
            int ar = tid >> 1, ac = (tid & 1) * 4;
            int arow = row0 + ar;
            float4 av = make_float4(0.f, 0.f, 0.f, 0.f);
            if (arow < M) av = *(const float4*)(A + (size_t)arow * K + k0 + ac);
            As[ac + 0][ar] = av.x; As[ac + 1][ar] = av.y;
            As[ac + 2][ar] = av.z; As[ac + 3][ar] = av.w;
        }
        {   // B tile: 8 k x 128 cols; thread -> row tid/32, cols (tid&31)*4
            int br = tid >> 5, bc = (tid & 31) * 4;
            *(float4*)&Bs[br][bc] = *(const float4*)(B + (size_t)(k0 + br) * N + col0 + bc);
        }
        __syncthreads();

        #pragma unroll
        for (int k = 0; k < 8; k++) {
            float a[8], b[8];
            #pragma unroll
            for (int i = 0; i < 8; i++) a[i] = As[k][ty * 8 + i];
            #pragma unroll
            for (int j = 0; j < 8; j++) b[j] = Bs[k][tx * 8 + j];
            #pragma unroll
            for (int i = 0; i < 8; i++)
                #pragma unroll
                for (int j = 0; j < 8; j++)
                    acc[i][j] += a[i] * b[j];
        }
        __syncthreads();
    }
    #pragma unroll
    for (int i = 0; i < 8; i++) {
        int row = row0 + ty * 8 + i;
        if (row < M) {
            *(float4*)(g_h1 + (size_t)row * N + col0 + tx * 8) =
                make_float4(acc[i][0], acc[i][1], acc[i][2], acc[i][3]);
            *(float4*)(g_h1 + (size_t)row * N + col0 + tx * 8 + 4) =
                make_float4(acc[i][4], acc[i][5], acc[i][6], acc[i][7]);
        }
    }
}

// ---------------- GEMM2: g_h2[M,128] = relu(g_agg1 + b1)[M,384] @ W2[384,128] ----
// BM=128, BN=64, BK=8, 256 threads, 8x4 microtile.
__global__ __launch_bounds__(256) void gemm_l2(const float* __restrict__ B,
                                               const float* __restrict__ abias, int M)
{
    const int N = 128, K = 384;
    __shared__ float As[8][132];
    __shared__ float Bs[8][64];
    const int tid = threadIdx.x;
    const int tx = tid & 15, ty = tid >> 4;       // 16x16 grid; tx covers 4 cols, ty 8 rows
    const int row0 = blockIdx.y * 128, col0 = blockIdx.x * 64;
    float acc[8][4] = {};

    for (int k0 = 0; k0 < K; k0 += 8) {
        {   // A tile with fused relu(x + b1)
            int ar = tid >> 1, ac = (tid & 1) * 4;
            int arow = row0 + ar;
            float4 av = make_float4(0.f, 0.f, 0.f, 0.f);
            if (arow < M) {
                av = *(const float4*)(g_agg1 + (size_t)arow * K + k0 + ac);
                av.x = fmaxf(av.x + abias[k0 + ac + 0], 0.f);
                av.y = fmaxf(av.y + abias[k0 + ac + 1], 0.f);
                av.z = fmaxf(av.z + abias[k0 + ac + 2], 0.f);
                av.w = fmaxf(av.w + abias[k0 + ac + 3], 0.f);
            }
            As[ac + 0][ar] = av.x; As[ac + 1][ar] = av.y;
            As[ac + 2][ar] = av.z; As[ac + 3][ar] = av.w;
        }
        if (tid < 128) {  // B tile: 8 k x 64 cols
            int br = tid >> 4, bc = (tid & 15) * 4;
            *(float4*)&Bs[br][bc] = *(const float4*)(B + (size_t)(k0 + br) * N + col0 + bc);
        }
        __syncthreads();

        #pragma unroll
        for (int k = 0; k < 8; k++) {
            float a[8], b[4];
            #pragma unroll
            for (int i = 0; i < 8; i++) a[i] = As[k][ty * 8 + i];
            #pragma unroll
            for (int j = 0; j < 4; j++) b[j] = Bs[k][tx * 4 + j];
            #pragma unroll
            for (int i = 0; i < 8; i++)
                #pragma unroll
                for (int j = 0; j < 4; j++)
                    acc[i][j] += a[i] * b[j];
        }
        __syncthreads();
    }
    #pragma unroll
    for (int i = 0; i < 8; i++) {
        int row = row0 + ty * 8 + i;
        if (row < M)
            *(float4*)(g_h2 + (size_t)row * N + col0 + tx * 4) =
                make_float4(acc[i][0], acc[i][1], acc[i][2], acc[i][3]);
    }
}

// ---------------- s/d: warp per (node,head), float4 + shuffle reduce ---------
__global__ void sd_l1(const float* __restrict__ asrc, const float* __restrict__ adst, int n)
{
    int w = (blockIdx.x * blockDim.x + threadIdx.x) >> 5;
    int lane = threadIdx.x & 31;
    if (w >= n * 3) return;
    int hd = w % 3;
    float4 hv = *(const float4*)(g_h1 + (size_t)w * 128 + lane * 4);
    float4 sa = *(const float4*)(asrc + hd * 128 + lane * 4);
    float4 da = *(const float4*)(adst + hd * 128 + lane * 4);
    float ss = hv.x * sa.x + hv.y * sa.y + hv.z * sa.z + hv.w * sa.w;
    float dd = hv.x * da.x + hv.y * da.y + hv.z * da.z + hv.w * da.w;
    #pragma unroll
    for (int o = 16; o; o >>= 1) {
        ss += __shfl_down_sync(0xffffffffu, ss, o);
        dd += __shfl_down_sync(0xffffffffu, dd, o);
    }
    if (lane == 0) { g_s1[w] = ss; g_d1[w] = dd; }
}

__global__ void sd_l2(const float* __restrict__ asrc, const float* __restrict__ adst, int n)
{
    int w = (blockIdx.x * blockDim.x + threadIdx.x) >> 5;
    int lane = threadIdx.x & 31;
    if (w >= n) return;
    float4 hv = *(const float4*)(g_h2 + (size_t)w * 128 + lane * 4);
    float4 sa = *(const float4*)(asrc + lane * 4);
    float4 da = *(const float4*)(adst + lane * 4);
    float ss = hv.x * sa.x + hv.y * sa.y + hv.z * sa.z + hv.w * sa.w;
    float dd = hv.x * da.x + hv.y * da.y + hv.z * da.z + hv.w * da.w;
    #pragma unroll
    for (int o = 16; o; o >>= 1) {
        ss += __shfl_down_sync(0xffffffffu, ss, o);
        dd += __shfl_down_sync(0xffffffffu, dd, o);
    }
    if (lane == 0) { g_s2[w] = ss; g_d2[w] = dd; }
}

// ---------------- layer-1 softmax + aggregation: warp per dst node -----------
__global__ __launch_bounds__(256) void agg_l1_csr(int E, int Ncnt,
                                                  float* __restrict__ out,
                                                  long long alpha_base, long long out_size)
{
    int dst = (blockIdx.x * blockDim.x + threadIdx.x) >> 5;
    int lane = threadIdx.x & 31;
    if (dst >= Ncnt) return;
    int beg = g_off[dst], end = g_off[dst + 1];

    float dv0 = g_d1[dst * 3 + 0], dv1 = g_d1[dst * 3 + 1], dv2 = g_d1[dst * 3 + 2];

    // pass A: exp + den (store raw exp into alpha slots)
    float den0 = 0.f, den1 = 0.f, den2 = 0.f;
    for (int i = beg + lane; i < end; i += 32) {
        int eid = g_eid[i];
        int src = g_esrc[i];
        float e0 = g_s1[src * 3 + 0] + dv0;
        float e1 = g_s1[src * 3 + 1] + dv1;
        float e2 = g_s1[src * 3 + 2] + dv2;
        e0 = e0 > 0.f ? e0 : 0.2f * e0;
        e1 = e1 > 0.f ? e1 : 0.2f * e1;
        e2 = e2 > 0.f ? e2 : 0.2f * e2;
        float x0 = expf(e0), x1 = expf(e1), x2 = expf(e2);
        long long ob = alpha_base + 3LL * eid;
        if (ob + 2 < out_size) { out[ob] = x0; out[ob + 1] = x1; out[ob + 2] = x2; }
        den0 += x0; den1 += x1; den2 += x2;
    }
    #pragma unroll
    for (int o = 16; o; o >>= 1) {
        den0 += __shfl_xor_sync(0xffffffffu, den0, o);
        den1 += __shfl_xor_sync(0xffffffffu, den1, o);
        den2 += __shfl_xor_sync(0xffffffffu, den2, o);
    }
    float r0 = 1.f / den0, r1 = 1.f / den1, r2 = 1.f / den2;
    __syncwarp();

    // pass B: normalize alpha (write), gather + accumulate
    float acc[12];
    #pragma unroll
    for (int k = 0; k < 12; k++) acc[k] = 0.f;
    float nat = 0.f;

    for (int i = beg; i < end; i++) {
        int eid = g_eid[i];
        int src = g_esrc[i];
        long long ob = alpha_base + 3LL * eid;
        float a0 = 0.f, a1 = 0.f, a2 = 0.f;
        if (ob + 2 < out_size) {
            a0 = out[ob] * r0; a1 = out[ob + 1] * r1; a2 = out[ob + 2] * r2;
            if (lane == 0) { out[ob] = a0; out[ob + 1] = a1; out[ob + 2] = a2; }
        }
        nat += (a0 + a1 + a2) * (1.0f / 3.0f);

        const float4* hs = (const float4*)(g_h1 + (size_t)src * 384);
        float4 v0 = hs[lane];
        float4 v1 = hs[32 + lane];
        float4 v2 = hs[64 + lane];
        acc[0] += v0.x * a0; acc[1]  += v0.y * a0; acc[2]  += v0.z * a0; acc[3]  += v0.w * a0;
        acc[4] += v1.x * a1; acc[5]  += v1.y * a1; acc[6]  += v1.z * a1; acc[7]  += v1.w * a1;
        acc[8] += v2.x * a2; acc[9]  += v2.y * a2; acc[10] += v2.z * a2; acc[11] += v2.w * a2;
    }

    if (lane == 0) g_nattn[dst] = nat;
    float4* og = (float4*)(g_agg1 + (size_t)dst * 384);
    og[lane]      = make_float4(acc[0], acc[1], acc[2], acc[3]);
    og[32 + lane] = make_float4(acc[4], acc[5], acc[6], acc[7]);
    og[64 + lane] = make_float4(acc[8], acc[9], acc[10], acc[11]);
}

// ---------------- layer-2 softmax + aggregation: warp per dst node -----------
__global__ __launch_bounds__(256) void agg_l2_csr(int E, int Ncnt)
{
    int dst = (blockIdx.x * blockDim.x + threadIdx.x) >> 5;
    int lane = threadIdx.x & 31;
    if (dst >= Ncnt) return;
    int beg = g_off[dst], end = g_off[dst + 1];

    float dv = g_d2[dst];
    float den = 0.f;
    for (int i = beg + lane; i < end; i += 32) {
        int eid = g_eid[i];
        int src = g_esrc[i];
        float e = g_s2[src] + dv;
        e = e > 0.f ? e : 0.2f * e;
        float x = expf(e);
        g_expe2[eid] = x;
        den += x;
    }
    #pragma unroll
    for (int o = 16; o; o >>= 1) den += __shfl_xor_sync(0xffffffffu, den, o);
    float r = 1.f / den;
    __syncwarp();

    float4 acc = make_float4(0.f, 0.f, 0.f, 0.f);
    for (int i = beg; i < end; i++) {
        int eid = g_eid[i];
        int src = g_esrc[i];
        float a = g_expe2[eid] * r;
        float4 v = ((const float4*)(g_h2 + (size_t)src * 128))[lane];
        acc.x += v.x * a; acc.y += v.y * a; acc.z += v.z * a; acc.w += v.w * a;
    }
    ((float4*)(g_agg2 + (size_t)dst * 128))[lane] = acc;
}

// ---------------- pooling into g_pool[pool_off .. pool_off+255] ---------------
__global__ void pool_kernel(const float* __restrict__ b2, int Ncnt, int pool_off)
{
    int c = blockIdx.x;  // 0..127
    float bias = b2[c];
    float sw = 0.f, se = 0.f;
    for (int n = threadIdx.x; n < Ncnt; n += blockDim.x) {
        float v = g_agg2[(size_t)n * 128 + c] + bias;
        se += v;
        sw += v * g_nattn[n];
    }
    __shared__ float r0[256], r1[256];
    r0[threadIdx.x] = sw; r1[threadIdx.x] = se;
    __syncthreads();
    for (int o = 128; o; o >>= 1) {
        if (threadIdx.x < o) { r0[threadIdx.x] += r0[threadIdx.x + o]; r1[threadIdx.x] += r1[threadIdx.x + o]; }
        __syncthreads();
    }
    if (threadIdx.x == 0) {
        float inv = 1.0f / (float)Ncnt;
        g_pool[pool_off + c]       = r0[0] * inv;
        g_pool[pool_off + 128 + c] = r1[0] * inv;
    }
}

// ---------------- cosine similarity (guarded write) ----------------
__global__ void sim_kernel(float* __restrict__ out, long long out_size)
{
    int t = threadIdx.x;  // 256 threads
    float a = g_pool[t], b = g_pool[256 + t];
    __shared__ float sd_[256], sa[256], sb[256];
    sd_[t] = a * b; sa[t] = a * a; sb[t] = b * b;
    __syncthreads();
    for (int o = 128; o; o >>= 1) {
        if (t < o) { sd_[t] += sd_[t + o]; sa[t] += sa[t + o]; sb[t] += sb[t + o]; }
        __syncthreads();
    }
    if (t == 0 && out_size >= 1) {
        float n1 = fmaxf(sqrtf(sa[0]), 1e-8f);
        float n2 = fmaxf(sqrtf(sb[0]), 1e-8f);
        out[0] = sd_[0] / (n1 * n2);
    }
}

// ---------------- host launcher: kernel launches ONLY ----------------
extern "C" void kernel_launch(void* const* d_in, const int* in_sizes, int n_in,
                              void* d_out, int out_size)
{
    const float* x1  = (const float*)d_in[0];
    const int*   ei1 = (const int*)d_in[1];     // int32
    const float* x2  = (const float*)d_in[2];
    const int*   ei2 = (const int*)d_in[3];
    const float* W1  = (const float*)d_in[4];
    const float* as1 = (const float*)d_in[5];
    const float* ad1 = (const float*)d_in[6];
    const float* b1  = (const float*)d_in[7];
    const float* W2  = (const float*)d_in[8];
    const float* as2 = (const float*)d_in[9];
    const float* ad2 = (const float*)d_in[10];
    const float* b2  = (const float*)d_in[11];
    float* out = (float*)d_out;
    const long long osz = (long long)out_size;

    const int Ncnt = in_sizes[0] / 256;
    const int E    = in_sizes[1] / 2;
    const int Etot = E + Ncnt;

    const int eblocks = (Etot + 255) / 256;
    const int nwarp_blocks = (Ncnt * 32 + 255) / 256;

    for (int b = 0; b < 2; b++) {
        const float* x  = b ? x2 : x1;
        const int*   ei = b ? ei2 : ei1;
        const long long alpha_base = 1 + (long long)b * Etot * 3;

        // CSR build (shared by both layers)
        zero_deg<<<(Ncnt + 255) / 256, 256>>>(Ncnt);
        csr_count<<<eblocks, 256>>>(ei, E, Ncnt);
        csr_scan<<<1, 1024>>>(Ncnt, Etot);
        csr_scatter<<<eblocks, 256>>>(ei, E, Ncnt);

        // layer 1
        gemm_l1<<<dim3(3, (Ncnt + 127) / 128), 256>>>(x, W1, Ncnt);
        sd_l1<<<(Ncnt * 3 * 32 + 255) / 256, 256>>>(as1, ad1, Ncnt);
        agg_l1_csr<<<nwarp_blocks, 256>>>(E, Ncnt, out, alpha_base, osz);

        // layer 2 (input = relu(agg1 + b1), fused into GEMM A-read)
        gemm_l2<<<dim3(2, (Ncnt + 127) / 128), 256>>>(W2, b1, Ncnt);
        sd_l2<<<(Ncnt * 32 + 255) / 256, 256>>>(as2, ad2, Ncnt);
        agg_l2_csr<<<nwarp_blocks, 256>>>(E, Ncnt);

        // pooling
        pool_kernel<<<128, 256>>>(b2, Ncnt, b * 256);
    }

    sim_kernel<<<1, 256>>>(out, osz);
}

// round 10
// speedup vs baseline: 1.8159x; 1.3372x over previous
#include <cuda_runtime.h>
#include <math.h>
#include <stdint.h>

#define NN    10000
#define EEMAX 320000
#define ETOTM (EEMAX + NN)

// ---------------- scratch: double-buffered per branch ----------------
__device__ __align__(16) float g_h1[2 * NN * 384];
__device__ __align__(16) float g_s1[2 * NN * 3];
__device__ __align__(16) float g_d1[2 * NN * 3];
__device__ __align__(16) float g_agg1[2 * NN * 384];
__device__ __align__(16) float g_h2[2 * NN * 128];
__device__ __align__(16) float g_s2[2 * NN];
__device__ __align__(16) float g_d2[2 * NN];
__device__ __align__(16) float g_exp1[2 * 3 * ETOTM];   // CSR-ordered, 3 planes per branch
__device__ __align__(16) float g_exp2[2 * ETOTM];        // CSR-ordered
__device__ __align__(16) float g_agg2[2 * NN * 128];
__device__ __align__(16) float g_nattn[2 * NN];
__device__ __align__(16) float g_pool[2 * 256];
// CSR per branch
__device__ int g_deg[2 * NN];
__device__ int g_off[2 * (NN + 1)];
__device__ int g_fill[2 * NN];
__device__ int g_eid[2 * ETOTM];
__device__ int g_esrc[2 * ETOTM];

// ---------------- CSR build (both branches in one launch) ----------------
__global__ void init_deg(int Ncnt)
{
    int i = blockIdx.x * blockDim.x + threadIdx.x;
    if (i < 2 * Ncnt) g_deg[i] = 0;
}

__global__ void csr_count(const int* __restrict__ ei1, const int* __restrict__ ei2,
                          int E, int Ncnt)
{
    int t = blockIdx.x * blockDim.x + threadIdx.x;
    int Etot = E + Ncnt;
    if (t >= 2 * Etot) return;
    int b = (t >= Etot) ? 1 : 0;
    int e = t - b * Etot;
    const int* ei = b ? ei2 : ei1;
    int dst = (e < E) ? ei[E + e] : (e - E);
    dst = min(max(dst, 0), Ncnt - 1);
    atomicAdd(&g_deg[b * NN + dst], 1);
}

// 2 blocks x 1024 threads: per-branch exclusive scan
__global__ void csr_scan(int Ncnt, int Etot)
{
    __shared__ int part[1024];
    int b = blockIdx.x;
    int* deg = g_deg + b * NN;
    int* off = g_off + b * (NN + 1);
    int* fil = g_fill + b * NN;
    int t = threadIdx.x;
    int chunk = (Ncnt + 1023) / 1024;
    int s0 = t * chunk;
    int s1 = min(s0 + chunk, Ncnt);
    int s = 0;
    for (int i = s0; i < s1; i++) s += deg[i];
    part[t] = s;
    __syncthreads();
    for (int o = 1; o < 1024; o <<= 1) {
        int v = (t >= o) ? part[t - o] : 0;
        __syncthreads();
        part[t] += v;
        __syncthreads();
    }
    int run = part[t] - s;
    for (int i = s0; i < s1; i++) {
        off[i] = run;
        fil[i] = run;
        run += deg[i];
    }
    if (t == 0) off[Ncnt] = Etot;
}

__global__ void csr_scatter(const int* __restrict__ ei1, const int* __restrict__ ei2,
                            int E, int Ncnt)
{
    int t = blockIdx.x * blockDim.x + threadIdx.x;
    int Etot = E + Ncnt;
    if (t >= 2 * Etot) return;
    int b = (t >= Etot) ? 1 : 0;
    int e = t - b * Etot;
    const int* ei = b ? ei2 : ei1;
    int src, dst;
    if (e < E) { src = ei[e]; dst = ei[E + e]; }
    else       { src = e - E; dst = src; }
    src = min(max(src, 0), Ncnt - 1);
    dst = min(max(dst, 0), Ncnt - 1);
    int pos = atomicAdd(&g_fill[b * NN + dst], 1);
    g_eid[b * ETOTM + pos] = e;
    g_esrc[b * ETOTM + pos] = src;
}

// ---------------- GEMM1: h1[b][M,384] = x_b[M,256] @ W1[256,384] ----------------
// BM=128, BN=128, BK=8, 256 threads, 8x8 microtile. blockIdx.z = branch.
__global__ __launch_bounds__(256) void gemm_l1(const float* __restrict__ A1,
                                               const float* __restrict__ A2,
                                               const float* __restrict__ B, int M)
{
    const int N = 384, K = 256;
    __shared__ float As[8][132];
    __shared__ float Bs[8][128];
    const int tid = threadIdx.x;
    const int tx = tid & 15, ty = tid >> 4;
    const int row0 = blockIdx.y * 128, col0 = blockIdx.x * 128;
    const float* A = blockIdx.z ? A2 : A1;
    float* H = g_h1 + (size_t)blockIdx.z * NN * 384;
    float acc[8][8] = {};

    for (int k0 = 0; k0 < K; k0 += 8) {
        {
            int ar = tid >> 1, ac = (tid & 1) * 4;
            int arow = row0 + ar;
            float4 av = make_float4(0.f, 0.f, 0.f, 0.f);
            if (arow < M) av = *(const float4*)(A + (size_t)arow * K + k0 + ac);
            As[ac + 0][ar] = av.x; As[ac + 1][ar] = av.y;
            As[ac + 2][ar] = av.z; As[ac + 3][ar] = av.w;
        }
        {
            int br = tid >> 5, bc = (tid & 31) * 4;
            *(float4*)&Bs[br][bc] = *(const float4*)(B + (size_t)(k0 + br) * N + col0 + bc);
        }
        __syncthreads();

        #pragma unroll
        for (int k = 0; k < 8; k++) {
            float a[8], b[8];
            #pragma unroll
            for (int i = 0; i < 8; i++) a[i] = As[k][ty * 8 + i];
            #pragma unroll
            for (int j = 0; j < 8; j++) b[j] = Bs[k][tx * 8 + j];
            #pragma unroll
            for (int i = 0; i < 8; i++)
                #pragma unroll
                for (int j = 0; j < 8; j++)
                    acc[i][j] += a[i] * b[j];
        }
        __syncthreads();
    }
    #pragma unroll
    for (int i = 0; i < 8; i++) {
        int row = row0 + ty * 8 + i;
        if (row < M) {
            *(float4*)(H + (size_t)row * N + col0 + tx * 8) =
                make_float4(acc[i][0], acc[i][1], acc[i][2], acc[i][3]);
            *(float4*)(H + (size_t)row * N + col0 + tx * 8 + 4) =
                make_float4(acc[i][4], acc[i][5], acc[i][6], acc[i][7]);
        }
    }
}

// ---------------- GEMM2: h2[b][M,128] = relu(agg1[b] + b1)[M,384] @ W2 ----------
__global__ __launch_bounds__(256) void gemm_l2(const float* __restrict__ B,
                                               const float* __restrict__ abias, int M)
{
    const int N = 128, K = 384;
    __shared__ float As[8][132];
    __shared__ float Bs[8][64];
    const int tid = threadIdx.x;
    const int tx = tid & 15, ty = tid >> 4;
    const int row0 = blockIdx.y * 128, col0 = blockIdx.x * 64;
    const float* AG = g_agg1 + (size_t)blockIdx.z * NN * 384;
    float* H = g_h2 + (size_t)blockIdx.z * NN * 128;
    float acc[8][4] = {};

    for (int k0 = 0; k0 < K; k0 += 8) {
        {
            int ar = tid >> 1, ac = (tid & 1) * 4;
            int arow = row0 + ar;
            float4 av = make_float4(0.f, 0.f, 0.f, 0.f);
            if (arow < M) {
                av = *(const float4*)(AG + (size_t)arow * K + k0 + ac);
                av.x = fmaxf(av.x + abias[k0 + ac + 0], 0.f);
                av.y = fmaxf(av.y + abias[k0 + ac + 1], 0.f);
                av.z = fmaxf(av.z + abias[k0 + ac + 2], 0.f);
                av.w = fmaxf(av.w + abias[k0 + ac + 3], 0.f);
            }
            As[ac + 0][ar] = av.x; As[ac + 1][ar] = av.y;
            As[ac + 2][ar] = av.z; As[ac + 3][ar] = av.w;
        }
        if (tid < 128) {
            int br = tid >> 4, bc = (tid & 15) * 4;
            *(float4*)&Bs[br][bc] = *(const float4*)(B + (size_t)(k0 + br) * N + col0 + bc);
        }
        __syncthreads();

        #pragma unroll
        for (int k = 0; k < 8; k++) {
            float a[8], b[4];
            #pragma unroll
            for (int i = 0; i < 8; i++) a[i] = As[k][ty * 8 + i];
            #pragma unroll
            for (int j = 0; j < 4; j++) b[j] = Bs[k][tx * 4 + j];
            #pragma unroll
            for (int i = 0; i < 8; i++)
                #pragma unroll
                for (int j = 0; j < 4; j++)
                    acc[i][j] += a[i] * b[j];
        }
        __syncthreads();
    }
    #pragma unroll
    for (int i = 0; i < 8; i++) {
        int row = row0 + ty * 8 + i;
        if (row < M)
            *(float4*)(H + (size_t)row * N + col0 + tx * 4) =
                make_float4(acc[i][0], acc[i][1], acc[i][2], acc[i][3]);
    }
}

// ---------------- s/d (both branches): warp per (b, node, head) ---------------
__global__ void sd_l1(const float* __restrict__ asrc, const float* __restrict__ adst, int n)
{
    int w = (blockIdx.x * blockDim.x + threadIdx.x) >> 5;
    int lane = threadIdx.x & 31;
    if (w >= 2 * n * 3) return;
    int b = w / (n * 3);
    int loc = w - b * n * 3;
    int hd = loc % 3;
    float4 hv = *(const float4*)(g_h1 + ((size_t)b * NN * 3 + loc) * 128 + lane * 4);
    float4 sa = *(const float4*)(asrc + hd * 128 + lane * 4);
    float4 da = *(const float4*)(adst + hd * 128 + lane * 4);
    float ss = hv.x * sa.x + hv.y * sa.y + hv.z * sa.z + hv.w * sa.w;
    float dd = hv.x * da.x + hv.y * da.y + hv.z * da.z + hv.w * da.w;
    #pragma unroll
    for (int o = 16; o; o >>= 1) {
        ss += __shfl_down_sync(0xffffffffu, ss, o);
        dd += __shfl_down_sync(0xffffffffu, dd, o);
    }
    if (lane == 0) { g_s1[b * NN * 3 + loc] = ss; g_d1[b * NN * 3 + loc] = dd; }
}

__global__ void sd_l2(const float* __restrict__ asrc, const float* __restrict__ adst, int n)
{
    int w = (blockIdx.x * blockDim.x + threadIdx.x) >> 5;
    int lane = threadIdx.x & 31;
    if (w >= 2 * n) return;
    int b = w / n;
    int loc = w - b * n;
    float4 hv = *(const float4*)(g_h2 + ((size_t)b * NN + loc) * 128 + lane * 4);
    float4 sa = *(const float4*)(asrc + lane * 4);
    float4 da = *(const float4*)(adst + lane * 4);
    float ss = hv.x * sa.x + hv.y * sa.y + hv.z * sa.z + hv.w * sa.w;
    float dd = hv.x * da.x + hv.y * da.y + hv.z * da.z + hv.w * da.w;
    #pragma unroll
    for (int o = 16; o; o >>= 1) {
        ss += __shfl_down_sync(0xffffffffu, ss, o);
        dd += __shfl_down_sync(0xffffffffu, dd, o);
    }
    if (lane == 0) { g_s2[b * NN + loc] = ss; g_d2[b * NN + loc] = dd; }
}

// ---------------- layer-1 softmax + aggregation: warp per dst, blockIdx.y = branch
__global__ __launch_bounds__(256) void agg_l1_csr(int E, int Ncnt,
                                                  float* __restrict__ out, long long out_size)
{
    int b = blockIdx.y;
    int dst = (blockIdx.x * blockDim.x + threadIdx.x) >> 5;
    int lane = threadIdx.x & 31;
    if (dst >= Ncnt) return;
    const int Etot = E + Ncnt;
    const int* off  = g_off + b * (NN + 1);
    const int* eidv = g_eid + b * ETOTM;
    const int* srcv = g_esrc + b * ETOTM;
    const float* s1 = g_s1 + b * NN * 3;
    float* e0p = g_exp1 + (size_t)(b * 3 + 0) * ETOTM;
    float* e1p = g_exp1 + (size_t)(b * 3 + 1) * ETOTM;
    float* e2p = g_exp1 + (size_t)(b * 3 + 2) * ETOTM;
    const long long alpha_base = 1 + (long long)b * Etot * 3;

    int beg = off[dst], end = off[dst + 1];
    float dv0 = g_d1[b * NN * 3 + dst * 3 + 0];
    float dv1 = g_d1[b * NN * 3 + dst * 3 + 1];
    float dv2 = g_d1[b * NN * 3 + dst * 3 + 2];

    // pass A: exp into coalesced CSR-ordered scratch + den
    float den0 = 0.f, den1 = 0.f, den2 = 0.f;
    for (int i = beg + lane; i < end; i += 32) {
        int src = srcv[i];
        float e0 = s1[src * 3 + 0] + dv0;
        float e1 = s1[src * 3 + 1] + dv1;
        float e2 = s1[src * 3 + 2] + dv2;
        e0 = e0 > 0.f ? e0 : 0.2f * e0;
        e1 = e1 > 0.f ? e1 : 0.2f * e1;
        e2 = e2 > 0.f ? e2 : 0.2f * e2;
        float x0 = expf(e0), x1 = expf(e1), x2 = expf(e2);
        e0p[i] = x0; e1p[i] = x1; e2p[i] = x2;
        den0 += x0; den1 += x1; den2 += x2;
    }
    #pragma unroll
    for (int o = 16; o; o >>= 1) {
        den0 += __shfl_xor_sync(0xffffffffu, den0, o);
        den1 += __shfl_xor_sync(0xffffffffu, den1, o);
        den2 += __shfl_xor_sync(0xffffffffu, den2, o);
    }
    float r0 = 1.f / den0, r1 = 1.f / den1, r2 = 1.f / den2;
    __syncwarp();

    // pass B1: normalize + write alpha to d_out (lane-parallel), accumulate nattn
    float nat = 0.f;
    for (int i = beg + lane; i < end; i += 32) {
        float a0 = e0p[i] * r0, a1 = e1p[i] * r1, a2 = e2p[i] * r2;
        long long ob = alpha_base + 3LL * eidv[i];
        if (ob + 2 < out_size) { out[ob] = a0; out[ob + 1] = a1; out[ob + 2] = a2; }
        nat += (a0 + a1 + a2) * (1.0f / 3.0f);
    }
    #pragma unroll
    for (int o = 16; o; o >>= 1) nat += __shfl_xor_sync(0xffffffffu, nat, o);
    if (lane == 0) g_nattn[b * NN + dst] = nat;

    // pass B2: gather h1[src] and accumulate
    float acc[12];
    #pragma unroll
    for (int k = 0; k < 12; k++) acc[k] = 0.f;
    const float4* h1b = (const float4*)(g_h1 + (size_t)b * NN * 384);

    #pragma unroll 2
    for (int i = beg; i < end; i++) {
        float a0 = e0p[i] * r0, a1 = e1p[i] * r1, a2 = e2p[i] * r2;  // broadcast
        int src = srcv[i];
        const float4* hs = h1b + (size_t)src * 96;
        float4 v0 = hs[lane];
        float4 v1 = hs[32 + lane];
        float4 v2 = hs[64 + lane];
        acc[0] += v0.x * a0; acc[1]  += v0.y * a0; acc[2]  += v0.z * a0; acc[3]  += v0.w * a0;
        acc[4] += v1.x * a1; acc[5]  += v1.y * a1; acc[6]  += v1.z * a1; acc[7]  += v1.w * a1;
        acc[8] += v2.x * a2; acc[9]  += v2.y * a2; acc[10] += v2.z * a2; acc[11] += v2.w * a2;
    }

    float4* og = (float4*)(g_agg1 + ((size_t)b * NN + dst) * 384);
    og[lane]      = make_float4(acc[0], acc[1], acc[2], acc[3]);
    og[32 + lane] = make_float4(acc[4], acc[5], acc[6], acc[7]);
    og[64 + lane] = make_float4(acc[8], acc[9], acc[10], acc[11]);
}

// ---------------- layer-2 softmax + aggregation ----------------
__global__ __launch_bounds__(256) void agg_l2_csr(int E, int Ncnt)
{
    int b = blockIdx.y;
    int dst = (blockIdx.x * blockDim.x + threadIdx.x) >> 5;
    int lane = threadIdx.x & 31;
    if (dst >= Ncnt) return;
    const int* off  = g_off + b * (NN + 1);
    const int* srcv = g_esrc + b * ETOTM;
    const float* s2 = g_s2 + b * NN;
    float* xp = g_exp2 + (size_t)b * ETOTM;

    int beg = off[dst], end = off[dst + 1];
    float dv = g_d2[b * NN + dst];
    float den = 0.f;
    for (int i = beg + lane; i < end; i += 32) {
        int src = srcv[i];
        float e = s2[src] + dv;
        e = e > 0.f ? e : 0.2f * e;
        float x = expf(e);
        xp[i] = x;
        den += x;
    }
    #pragma unroll
    for (int o = 16; o; o >>= 1) den += __shfl_xor_sync(0xffffffffu, den, o);
    float r = 1.f / den;
    __syncwarp();

    float4 acc = make_float4(0.f, 0.f, 0.f, 0.f);
    const float4* h2b = (const float4*)(g_h2 + (size_t)b * NN * 128);
    #pragma unroll 2
    for (int i = beg; i < end; i++) {
        float a = xp[i] * r;
        int src = srcv[i];
        float4 v = h2b[(size_t)src * 32 + lane];
        acc.x += v.x * a; acc.y += v.y * a; acc.z += v.z * a; acc.w += v.w * a;
    }
    ((float4*)(g_agg2 + ((size_t)b * NN + dst) * 128))[lane] = acc;
}

// ---------------- pooling: grid (128, 2) ----------------
__global__ void pool_kernel(const float* __restrict__ b2, int Ncnt)
{
    int c = blockIdx.x;
    int b = blockIdx.y;
    const float* ag = g_agg2 + (size_t)b * NN * 128;
    const float* na = g_nattn + b * NN;
    float bias = b2[c];
    float sw = 0.f, se = 0.f;
    for (int n = threadIdx.x; n < Ncnt; n += blockDim.x) {
        float v = ag[(size_t)n * 128 + c] + bias;
        se += v;
        sw += v * na[n];
    }
    __shared__ float r0[256], r1[256];
    r0[threadIdx.x] = sw; r1[threadIdx.x] = se;
    __syncthreads();
    for (int o = 128; o; o >>= 1) {
        if (threadIdx.x < o) { r0[threadIdx.x] += r0[threadIdx.x + o]; r1[threadIdx.x] += r1[threadIdx.x + o]; }
        __syncthreads();
    }
    if (threadIdx.x == 0) {
        float inv = 1.0f / (float)Ncnt;
        g_pool[b * 256 + c]       = r0[0] * inv;
        g_pool[b * 256 + 128 + c] = r1[0] * inv;
    }
}

// ---------------- cosine similarity ----------------
__global__ void sim_kernel(float* __restrict__ out, long long out_size)
{
    int t = threadIdx.x;
    float a = g_pool[t], b = g_pool[256 + t];
    __shared__ float sd_[256], sa[256], sb[256];
    sd_[t] = a * b; sa[t] = a * a; sb[t] = b * b;
    __syncthreads();
    for (int o = 128; o; o >>= 1) {
        if (t < o) { sd_[t] += sd_[t + o]; sa[t] += sa[t + o]; sb[t] += sb[t + o]; }
        __syncthreads();
    }
    if (t == 0 && out_size >= 1) {
        float n1 = fmaxf(sqrtf(sa[0]), 1e-8f);
        float n2 = fmaxf(sqrtf(sb[0]), 1e-8f);
        out[0] = sd_[0] / (n1 * n2);
    }
}

// ---------------- host launcher ----------------
extern "C" void kernel_launch(void* const* d_in, const int* in_sizes, int n_in,
                              void* d_out, int out_size)
{
    const float* x1  = (const float*)d_in[0];
    const int*   ei1 = (const int*)d_in[1];     // int32
    const float* x2  = (const float*)d_in[2];
    const int*   ei2 = (const int*)d_in[3];
    const float* W1  = (const float*)d_in[4];
    const float* as1 = (const float*)d_in[5];
    const float* ad1 = (const float*)d_in[6];
    const float* b1  = (const float*)d_in[7];
    const float* W2  = (const float*)d_in[8];
    const float* as2 = (const float*)d_in[9];
    const float* ad2 = (const float*)d_in[10];
    const float* b2  = (const float*)d_in[11];
    float* out = (float*)d_out;
    const long long osz = (long long)out_size;

    const int Ncnt = in_sizes[0] / 256;
    const int E    = in_sizes[1] / 2;
    const int Etot = E + Ncnt;

    const int e2blocks = (2 * Etot + 255) / 256;
    const int nwb = (Ncnt * 32 + 255) / 256;     // warp-per-dst blocks (x-dim)

    // CSR build, both branches fused
    init_deg<<<(2 * Ncnt + 255) / 256, 256>>>(Ncnt);
    csr_count<<<e2blocks, 256>>>(ei1, ei2, E, Ncnt);
    csr_scan<<<2, 1024>>>(Ncnt, Etot);
    csr_scatter<<<e2blocks, 256>>>(ei1, ei2, E, Ncnt);

    // layer 1 (both branches)
    gemm_l1<<<dim3(3, (Ncnt + 127) / 128, 2), 256>>>(x1, x2, W1, Ncnt);
    sd_l1<<<(2 * Ncnt * 3 * 32 + 255) / 256, 256>>>(as1, ad1, Ncnt);
    agg_l1_csr<<<dim3(nwb, 2), 256>>>(E, Ncnt, out, osz);

    // layer 2 (both branches)
    gemm_l2<<<dim3(2, (Ncnt + 127) / 128, 2), 256>>>(W2, b1, Ncnt);
    sd_l2<<<(2 * Ncnt * 32 + 255) / 256, 256>>>(as2, ad2, Ncnt);
    agg_l2_csr<<<dim3(nwb, 2), 256>>>(E, Ncnt);

    // pooling + similarity
    pool_kernel<<<dim3(128, 2), 256>>>(b2, Ncnt);
    sim_kernel<<<1, 256>>>(out, osz);
}